// round 1
// baseline (speedup 1.0000x reference)
#include <cuda_runtime.h>
#include <math.h>

// Problem constants (fixed by setup_inputs)
#define BATCH 2
#define E     160000
#define NN    10000
#define FIN   24
#define D     128
#define RPB   16       // rows per block for GEMM-ish kernels

// ---------------- device scratch (no allocs allowed) ----------------
__device__ float g_edge_emb[BATCH * E * D];        // 163.8 MB
__device__ float g_se[2][BATCH * E];               // per-round edge attention term
__device__ float g_node[BATCH * NN * D];           // node embeddings
__device__ float g_P1[BATCH * NN * 256];           // node @ dec_w1[0:128]
__device__ float g_P2[BATCH * NN * 256];           // node @ dec_w1[128:256]
__device__ int   g_cnt[NN];
__device__ int   g_cur[NN];
__device__ int   g_off[NN + 1];
__device__ int   g_plist[2 * E];

// ---------------- helpers ----------------
__device__ __forceinline__ float gelu_exact(float x) {
    return 0.5f * x * (1.0f + erff(x * 0.70710678118654752f));
}

// sum across a 16-lane group (lanes [0,16) or [16,32) of a warp)
__device__ __forceinline__ float red16(float v) {
    v += __shfl_xor_sync(0xffffffffu, v, 8);
    v += __shfl_xor_sync(0xffffffffu, v, 4);
    v += __shfl_xor_sync(0xffffffffu, v, 2);
    v += __shfl_xor_sync(0xffffffffu, v, 1);
    return v;
}

__device__ __forceinline__ float red32(float v) {
    v += __shfl_xor_sync(0xffffffffu, v, 16);
    v += __shfl_xor_sync(0xffffffffu, v, 8);
    v += __shfl_xor_sync(0xffffffffu, v, 4);
    v += __shfl_xor_sync(0xffffffffu, v, 2);
    v += __shfl_xor_sync(0xffffffffu, v, 1);
    return v;
}

// ---------------- encoder: x[24] -> LN(gelu?) ... -> edge_emb[128], se1, se2 ----------------
// block: 256 threads, 16 rows. thread t: row r=t>>4, col group c0=t&15 (cols c0+16j)
__global__ __launch_bounds__(256) void enc_kernel(
    const float* __restrict__ xin,
    const float* __restrict__ w1, const float* __restrict__ b1,
    const float* __restrict__ g1, const float* __restrict__ be1,
    const float* __restrict__ w2, const float* __restrict__ b2,
    const float* __restrict__ g2, const float* __restrict__ be2,
    const float* __restrict__ watt1, const float* __restrict__ watt2)
{
    __shared__ float xS[RPB * FIN];          // 384
    __shared__ float W1S[FIN * D];           // 3072
    __shared__ float ghS[RPB * 129];         // padded, 2064
    __shared__ float W2S[32 * D];            // 4096 (chunked)
    __shared__ float vS[8 * 128];            // b1,g1,be1,b2,g2,be2,wh1,wh2

    int t = threadIdx.x;
    int r = t >> 4, c0 = t & 15;
    int base_row = blockIdx.x * RPB;

    for (int i = t; i < RPB * FIN; i += 256) {
        int rr = i / FIN, k = i % FIN;
        xS[i] = xin[(base_row + rr) * FIN + k];
    }
    for (int i = t; i < FIN * D; i += 256) W1S[i] = w1[i];
    if (t < 128) {
        vS[t]       = b1[t];  vS[128 + t] = g1[t];  vS[256 + t] = be1[t];
        vS[384 + t] = b2[t];  vS[512 + t] = g2[t];  vS[640 + t] = be2[t];
        vS[768 + t] = watt1[128 + t];  vS[896 + t] = watt2[128 + t];
    }
    __syncthreads();

    // GEMM1: [24] -> [128]
    float acc[8];
#pragma unroll
    for (int j = 0; j < 8; j++) acc[j] = vS[c0 + 16 * j];  // + b1
#pragma unroll
    for (int k = 0; k < FIN; k++) {
        float a = xS[r * FIN + k];
#pragma unroll
        for (int j = 0; j < 8; j++) acc[j] += a * W1S[k * D + c0 + 16 * j];
    }
    // LN1
    float s = 0.f, ss = 0.f;
#pragma unroll
    for (int j = 0; j < 8; j++) { s += acc[j]; ss += acc[j] * acc[j]; }
    s = red16(s); ss = red16(ss);
    float mu = s * (1.0f / 128.0f);
    float var = ss * (1.0f / 128.0f) - mu * mu;
    float inv = rsqrtf(var + 1e-5f);
#pragma unroll
    for (int j = 0; j < 8; j++) {
        int col = c0 + 16 * j;
        float h = (acc[j] - mu) * inv * vS[128 + col] + vS[256 + col];
        ghS[r * 129 + col] = gelu_exact(h);
    }

    // GEMM2: [128] -> [128], W2 chunked 32 rows at a time
#pragma unroll
    for (int j = 0; j < 8; j++) acc[j] = vS[384 + c0 + 16 * j];  // + b2
    for (int kc = 0; kc < 4; kc++) {
        __syncthreads();
        for (int i = t; i < 32 * D; i += 256) W2S[i] = w2[kc * 32 * D + i];
        __syncthreads();
#pragma unroll
        for (int k = 0; k < 32; k++) {
            float a = ghS[r * 129 + kc * 32 + k];
#pragma unroll
            for (int j = 0; j < 8; j++) acc[j] += a * W2S[k * D + c0 + 16 * j];
        }
    }
    // LN2
    s = 0.f; ss = 0.f;
#pragma unroll
    for (int j = 0; j < 8; j++) { s += acc[j]; ss += acc[j] * acc[j]; }
    s = red16(s); ss = red16(ss);
    mu = s * (1.0f / 128.0f);
    var = ss * (1.0f / 128.0f) - mu * mu;
    inv = rsqrtf(var + 1e-5f);

    int row = base_row + r;
    float p1 = 0.f, p2 = 0.f;
#pragma unroll
    for (int j = 0; j < 8; j++) {
        int col = c0 + 16 * j;
        float e = (acc[j] - mu) * inv * vS[512 + col] + vS[640 + col];
        g_edge_emb[row * D + col] = e;
        p1 += e * vS[768 + col];
        p2 += e * vS[896 + col];
    }
    p1 = red16(p1); p2 = red16(p2);
    if (c0 == 0) { g_se[0][row] = p1; g_se[1][row] = p2; }
}

// ---------------- CSR build ----------------
__global__ void zero_kernel() {
    int i = blockIdx.x * blockDim.x + threadIdx.x;
    if (i < BATCH * NN * D) g_node[i] = 0.f;
    if (i < NN) { g_cnt[i] = 0; g_cur[i] = 0; }
}

__global__ void hist_kernel(const int* __restrict__ src, const int* __restrict__ dst) {
    int p = blockIdx.x * blockDim.x + threadIdx.x;
    if (p >= 2 * E) return;
    int n = (p < E) ? src[p] : dst[p - E];
    atomicAdd(&g_cnt[n], 1);
}

__global__ __launch_bounds__(1024) void scan_kernel() {
    __shared__ int tot[1024];
    const int PT = 10;  // 1024*10 >= 10000
    int t = threadIdx.x;
    int base = t * PT;
    int loc[PT];
    int s = 0;
#pragma unroll
    for (int i = 0; i < PT; i++) {
        int idx = base + i;
        int v = (idx < NN) ? g_cnt[idx] : 0;
        loc[i] = s; s += v;
    }
    tot[t] = s;
    __syncthreads();
    for (int o = 1; o < 1024; o <<= 1) {
        int v = (t >= o) ? tot[t - o] : 0;
        __syncthreads();
        tot[t] += v;
        __syncthreads();
    }
    int excl = (t == 0) ? 0 : tot[t - 1];
#pragma unroll
    for (int i = 0; i < PT; i++) {
        int idx = base + i;
        if (idx < NN) g_off[idx] = excl + loc[i];
    }
    if (t == 1023) g_off[NN] = tot[1023];
}

__global__ void scatter_kernel(const int* __restrict__ src, const int* __restrict__ dst) {
    int p = blockIdx.x * blockDim.x + threadIdx.x;
    if (p >= 2 * E) return;
    int n = (p < E) ? src[p] : dst[p - E];
    int pos = atomicAdd(&g_cur[n], 1);
    g_plist[g_off[n] + pos] = p;
}

// ---------------- message passing: one warp per node ----------------
__global__ __launch_bounds__(256) void mp_kernel(
    const float* __restrict__ watt, const float* __restrict__ batt_p, int round)
{
    int w = threadIdx.x >> 5, lane = threadIdx.x & 31;
    int n = blockIdx.x * 8 + w;
    int b = blockIdx.y;
    if (n >= NN) return;
    int off = g_off[n];
    int cnt = g_off[n + 1] - off;
    if (cnt == 0) return;   // deg==0: keep previous node value

    float batt = batt_p[0];
    float* nrow = g_node + (b * NN + n) * D;

    // sn = node[n] . watt[0:128]
    float4 nv = reinterpret_cast<float4*>(nrow)[lane];
    float4 wv = reinterpret_cast<const float4*>(watt)[lane];
    float sn = nv.x * wv.x + nv.y * wv.y + nv.z * wv.z + nv.w * wv.w;
    sn = red32(sn);

    const float* se = g_se[round] + b * E;

    // online max + denominator, lane-strided over pairs
    float m = -1e30f, d = 0.f;
    for (int i = lane; i < cnt; i += 32) {
        int p = g_plist[off + i];
        int e = (p < E) ? p : p - E;
        float sv = sn + se[e] + batt;
        sv = (sv > 0.f) ? sv : 0.2f * sv;
        if (sv > m) { d = d * __expf(m - sv) + 1.f; m = sv; }
        else        { d += __expf(sv - m); }
    }
#pragma unroll
    for (int o = 16; o > 0; o >>= 1) {
        float mo = __shfl_xor_sync(0xffffffffu, m, o);
        float dq = __shfl_xor_sync(0xffffffffu, d, o);
        float M = fmaxf(m, mo);
        d = d * __expf(m - M) + dq * __expf(mo - M);
        m = M;
    }
    float invd = 1.0f / d;

    // weighted aggregation: all 32 lanes cooperate per pair (float4 over 128 dims)
    float4 acc = make_float4(0.f, 0.f, 0.f, 0.f);
    for (int i = 0; i < cnt; i++) {
        int p = g_plist[off + i];
        int e = (p < E) ? p : p - E;
        float sv = sn + se[e] + batt;
        sv = (sv > 0.f) ? sv : 0.2f * sv;
        float wt = __expf(sv - m) * invd;
        float4 ev = reinterpret_cast<const float4*>(g_edge_emb + (b * E + e) * D)[lane];
        acc.x += wt * ev.x; acc.y += wt * ev.y; acc.z += wt * ev.z; acc.w += wt * ev.w;
    }
    float4 outv;
    outv.x = gelu_exact(acc.x); outv.y = gelu_exact(acc.y);
    outv.z = gelu_exact(acc.z); outv.w = gelu_exact(acc.w);
    reinterpret_cast<float4*>(nrow)[lane] = outv;
}

// ---------------- node-side decoder precompute: P1/P2 = node @ dec_w1[part] ----------------
// grid: (NN/16, 2 /*part*/, BATCH); block 256
__global__ __launch_bounds__(256) void p_kernel(const float* __restrict__ dec_w1) {
    __shared__ float nodeS[RPB * 129];   // 2064
    __shared__ float WS[16 * 256];       // 4096 (chunked K=16)

    int t = threadIdx.x;
    int r = t >> 4, c0 = t & 15;
    int b = blockIdx.z, c = blockIdx.y;
    int n0 = blockIdx.x * RPB;

    for (int i = t; i < RPB * D; i += 256) {
        int rr = i >> 7, k = i & 127;
        nodeS[rr * 129 + k] = g_node[(b * NN + n0 + rr) * D + k];
    }
    float acc[16];
#pragma unroll
    for (int j = 0; j < 16; j++) acc[j] = 0.f;

    const float* Wbase = dec_w1 + c * D * 256;  // rows [c*128, c*128+128)
    for (int kc = 0; kc < 8; kc++) {
        __syncthreads();
        for (int i = t; i < 16 * 256; i += 256) WS[i] = Wbase[kc * 16 * 256 + i];
        __syncthreads();
#pragma unroll
        for (int k = 0; k < 16; k++) {
            float a = nodeS[r * 129 + kc * 16 + k];
#pragma unroll
            for (int j = 0; j < 16; j++) acc[j] += a * WS[k * 256 + c0 + 16 * j];
        }
    }
    float* P = (c == 0 ? g_P1 : g_P2) + (b * NN + n0 + r) * 256;
#pragma unroll
    for (int j = 0; j < 16; j++) P[c0 + 16 * j] = acc[j];
}

// ---------------- fused decoder ----------------
// z1 = gelu(P1[src] + P2[dst] + edge_emb @ W1c + b1); z2 = gelu(z1@W2+b2); out = z2.w3 + b3
__global__ __launch_bounds__(256) void dec_kernel(
    const float* __restrict__ dec_w1, const float* __restrict__ db1,
    const float* __restrict__ dec_w2, const float* __restrict__ db2,
    const float* __restrict__ dw3,    const float* __restrict__ db3,
    const int* __restrict__ src, const int* __restrict__ dst,
    float* __restrict__ out)
{
    __shared__ float embS[RPB * 129];   // 2064
    __shared__ float WS[16 * 256];      // 4096, reused as [32][128] in phase B
    __shared__ float z1S[RPB * 257];    // 4112
    __shared__ int srcS[RPB], dstS[RPB];

    int t = threadIdx.x;
    int r = t >> 4, c0 = t & 15;
    int g0 = blockIdx.x * RPB;

    for (int i = t; i < RPB * D; i += 256) {
        int rr = i >> 7, k = i & 127;
        embS[rr * 129 + k] = g_edge_emb[(g0 + rr) * D + k];
    }
    if (t < RPB) {
        int e = (g0 + t) % E;
        srcS[t] = src[e]; dstS[t] = dst[e];
    }

    // phase A: z1 += edge_emb @ W1c  (W1c = dec_w1 rows 256..383)
    float acc[16];
#pragma unroll
    for (int j = 0; j < 16; j++) acc[j] = 0.f;
    const float* W1c = dec_w1 + 256 * 256;
    for (int kc = 0; kc < 8; kc++) {
        __syncthreads();
        for (int i = t; i < 16 * 256; i += 256) WS[i] = W1c[kc * 16 * 256 + i];
        __syncthreads();
#pragma unroll
        for (int k = 0; k < 16; k++) {
            float a = embS[r * 129 + kc * 16 + k];
#pragma unroll
            for (int j = 0; j < 16; j++) acc[j] += a * WS[k * 256 + c0 + 16 * j];
        }
    }
    int g = g0 + r;
    int b = g / E;
    const float* P1r = g_P1 + (b * NN + srcS[r]) * 256;
    const float* P2r = g_P2 + (b * NN + dstS[r]) * 256;
#pragma unroll
    for (int j = 0; j < 16; j++) {
        int col = c0 + 16 * j;
        float z = acc[j] + db1[col] + P1r[col] + P2r[col];
        z1S[r * 257 + col] = gelu_exact(z);
    }

    // phase B: z2 = gelu(z1 @ W2 + b2), W2 chunked 32 rows (32*128 = 4096)
    float a2[8];
#pragma unroll
    for (int j = 0; j < 8; j++) a2[j] = 0.f;
    for (int kc = 0; kc < 8; kc++) {
        __syncthreads();
        for (int i = t; i < 32 * D; i += 256) WS[i] = dec_w2[kc * 32 * D + i];
        __syncthreads();
#pragma unroll
        for (int k = 0; k < 32; k++) {
            float a = z1S[r * 257 + kc * 32 + k];
#pragma unroll
            for (int j = 0; j < 8; j++) a2[j] += a * WS[k * D + c0 + 16 * j];
        }
    }
    float part = 0.f;
#pragma unroll
    for (int j = 0; j < 8; j++) {
        int col = c0 + 16 * j;
        part += gelu_exact(a2[j] + db2[col]) * dw3[col];
    }
    part = red16(part);
    if (c0 == 0) out[g] = part + db3[0];
}

// ---------------- launch ----------------
extern "C" void kernel_launch(void* const* d_in, const int* in_sizes, int n_in,
                              void* d_out, int out_size)
{
    const float* xf    = (const float*)d_in[0];
    const float* w1    = (const float*)d_in[1];
    const float* b1    = (const float*)d_in[2];
    const float* g1    = (const float*)d_in[3];
    const float* be1   = (const float*)d_in[4];
    const float* w2    = (const float*)d_in[5];
    const float* b2    = (const float*)d_in[6];
    const float* g2    = (const float*)d_in[7];
    const float* be2   = (const float*)d_in[8];
    const float* watt1 = (const float*)d_in[9];
    const float* batt1 = (const float*)d_in[10];
    const float* watt2 = (const float*)d_in[11];
    const float* batt2 = (const float*)d_in[12];
    const float* dw1   = (const float*)d_in[13];
    const float* db1   = (const float*)d_in[14];
    const float* dw2   = (const float*)d_in[15];
    const float* db2   = (const float*)d_in[16];
    const float* dw3   = (const float*)d_in[17];
    const float* db3   = (const float*)d_in[18];
    const int*   src   = (const int*)d_in[19];
    const int*   dst   = (const int*)d_in[20];
    float* out = (float*)d_out;

    // encoder (independent of CSR build)
    enc_kernel<<<(BATCH * E) / RPB, 256>>>(xf, w1, b1, g1, be1, w2, b2, g2, be2, watt1, watt2);

    // CSR build + node init
    zero_kernel<<<(BATCH * NN * D + 255) / 256, 256>>>();
    hist_kernel<<<(2 * E + 255) / 256, 256>>>(src, dst);
    scan_kernel<<<1, 1024>>>();
    scatter_kernel<<<(2 * E + 255) / 256, 256>>>(src, dst);

    // two rounds of message passing (in-place node update is safe:
    // node n reads only its own row + edge rows, writes only its own row)
    mp_kernel<<<dim3(NN / 8, BATCH), 256>>>(watt1, batt1, 0);
    mp_kernel<<<dim3(NN / 8, BATCH), 256>>>(watt2, batt2, 1);

    // node-side decoder precompute
    p_kernel<<<dim3(NN / RPB, 2, BATCH), 256>>>(dw1);

    // fused per-edge decoder
    dec_kernel<<<(BATCH * E) / RPB, 256>>>(dw1, db1, dw2, db2, dw3, db3, src, dst, out);
}

// round 2
// speedup vs baseline: 1.2557x; 1.2557x over previous
#include <cuda_runtime.h>
#include <math.h>

// Problem constants (fixed by setup_inputs)
#define BATCH 2
#define E     160000
#define NN    10000
#define FIN   24
#define D     128
#define RPB   16

// ---------------- device scratch (no allocs allowed) ----------------
__device__ float4 g_edge_emb4[BATCH * E * 32];     // 163.8 MB  [row][128]
__device__ float4 g_z1_4[BATCH * E * 64];          // 327.7 MB  [row][256]
__device__ float  g_se[2][BATCH * E];
__device__ float4 g_node4[BATCH * NN * 32];        // [b][n][128]
__device__ float4 g_P1_4[BATCH * NN * 64];         // node @ dec_w1[0:128]   -> [256]
__device__ float4 g_P2_4[BATCH * NN * 64];         // node @ dec_w1[128:256] -> [256]
__device__ int    g_cnt[NN];
__device__ int    g_cur[NN];
__device__ int    g_off[NN + 1];
__device__ int    g_plist[2 * E];

// ---------------- helpers ----------------
__device__ __forceinline__ float gelu_exact(float x) {
    return 0.5f * x * (1.0f + erff(x * 0.70710678118654752f));
}
__device__ __forceinline__ float red16(float v) {
    v += __shfl_xor_sync(0xffffffffu, v, 8);
    v += __shfl_xor_sync(0xffffffffu, v, 4);
    v += __shfl_xor_sync(0xffffffffu, v, 2);
    v += __shfl_xor_sync(0xffffffffu, v, 1);
    return v;
}
__device__ __forceinline__ float red32(float v) {
    v += __shfl_xor_sync(0xffffffffu, v, 16);
    v += __shfl_xor_sync(0xffffffffu, v, 8);
    v += __shfl_xor_sync(0xffffffffu, v, 4);
    v += __shfl_xor_sync(0xffffffffu, v, 2);
    v += __shfl_xor_sync(0xffffffffu, v, 1);
    return v;
}
// packed fp32x2 FMA (sm_100+): d = a*b + d, per 32-bit half, rn — identical to 2x fmaf
__device__ __forceinline__ void ffma2(unsigned long long& d, unsigned long long a, unsigned long long b) {
    asm("fma.rn.f32x2 %0, %1, %2, %0;" : "+l"(d) : "l"(a), "l"(b));
}
__device__ __forceinline__ unsigned long long pack2(float a) {
    unsigned long long r; unsigned u = __float_as_uint(a);
    asm("mov.b64 %0, {%1, %1};" : "=l"(r) : "r"(u));
    return r;
}
__device__ __forceinline__ float2 unpack2(unsigned long long v) {
    unsigned lo, hi;
    asm("mov.b64 {%0, %1}, %2;" : "=r"(lo), "=r"(hi) : "l"(v));
    return make_float2(__uint_as_float(lo), __uint_as_float(hi));
}

// ---------------- encoder ----------------
// block: 256 threads, 16 rows. thread: row r=t>>4, cols c0*8 .. c0*8+7 (c0=t&15)
__global__ __launch_bounds__(256) void enc_kernel(
    const float* __restrict__ xin,
    const float* __restrict__ w1, const float* __restrict__ b1,
    const float* __restrict__ g1, const float* __restrict__ be1,
    const float* __restrict__ w2, const float* __restrict__ b2,
    const float* __restrict__ g2, const float* __restrict__ be2,
    const float* __restrict__ watt1, const float* __restrict__ watt2)
{
    __shared__ alignas(16) float xS[RPB * FIN];
    __shared__ alignas(16) float W1S[FIN * D];
    __shared__ float ghS[RPB * 129];
    __shared__ alignas(16) float W2S[32 * D];
    __shared__ alignas(16) float vS[8 * 128];

    int t = threadIdx.x;
    int r = t >> 4, c0 = t & 15;
    int base_row = blockIdx.x * RPB;

    for (int i = t; i < RPB * FIN; i += 256) {
        int rr = i / FIN, k = i % FIN;
        xS[i] = xin[(base_row + rr) * FIN + k];
    }
    for (int i = t; i < FIN * D / 4; i += 256)
        ((float4*)W1S)[i] = ((const float4*)w1)[i];
    if (t < 128) {
        vS[t]       = b1[t];  vS[128 + t] = g1[t];  vS[256 + t] = be1[t];
        vS[384 + t] = b2[t];  vS[512 + t] = g2[t];  vS[640 + t] = be2[t];
        vS[768 + t] = watt1[128 + t];  vS[896 + t] = watt2[128 + t];
    }
    __syncthreads();

    // GEMM1: [24] -> [128]
    unsigned long long acc[4] = {0ull, 0ull, 0ull, 0ull};
#pragma unroll
    for (int k = 0; k < FIN; k++) {
        unsigned long long ap = pack2(xS[r * FIN + k]);
        ulonglong2 w01 = *(const ulonglong2*)&W1S[k * D + c0 * 8];
        ulonglong2 w23 = *(const ulonglong2*)&W1S[k * D + c0 * 8 + 4];
        ffma2(acc[0], ap, w01.x); ffma2(acc[1], ap, w01.y);
        ffma2(acc[2], ap, w23.x); ffma2(acc[3], ap, w23.y);
    }
    float v[8];
    {
        float2 u;
        u = unpack2(acc[0]); v[0] = u.x; v[1] = u.y;
        u = unpack2(acc[1]); v[2] = u.x; v[3] = u.y;
        u = unpack2(acc[2]); v[4] = u.x; v[5] = u.y;
        u = unpack2(acc[3]); v[6] = u.x; v[7] = u.y;
    }
#pragma unroll
    for (int j = 0; j < 8; j++) v[j] += vS[c0 * 8 + j];
    // LN1
    float s = 0.f, ss = 0.f;
#pragma unroll
    for (int j = 0; j < 8; j++) { s += v[j]; ss += v[j] * v[j]; }
    s = red16(s); ss = red16(ss);
    float mu = s * (1.0f / 128.0f);
    float var = ss * (1.0f / 128.0f) - mu * mu;
    float inv = rsqrtf(var + 1e-5f);
#pragma unroll
    for (int j = 0; j < 8; j++) {
        int col = c0 * 8 + j;
        float h = (v[j] - mu) * inv * vS[128 + col] + vS[256 + col];
        ghS[r * 129 + col] = gelu_exact(h);
    }

    // GEMM2: [128] -> [128]
    acc[0] = acc[1] = acc[2] = acc[3] = 0ull;
    for (int kc = 0; kc < 4; kc++) {
        __syncthreads();
        for (int i = t; i < 32 * D / 4; i += 256)
            ((float4*)W2S)[i] = ((const float4*)(w2 + kc * 32 * D))[i];
        __syncthreads();
#pragma unroll
        for (int k = 0; k < 32; k++) {
            unsigned long long ap = pack2(ghS[r * 129 + kc * 32 + k]);
            ulonglong2 w01 = *(const ulonglong2*)&W2S[k * D + c0 * 8];
            ulonglong2 w23 = *(const ulonglong2*)&W2S[k * D + c0 * 8 + 4];
            ffma2(acc[0], ap, w01.x); ffma2(acc[1], ap, w01.y);
            ffma2(acc[2], ap, w23.x); ffma2(acc[3], ap, w23.y);
        }
    }
    {
        float2 u;
        u = unpack2(acc[0]); v[0] = u.x; v[1] = u.y;
        u = unpack2(acc[1]); v[2] = u.x; v[3] = u.y;
        u = unpack2(acc[2]); v[4] = u.x; v[5] = u.y;
        u = unpack2(acc[3]); v[6] = u.x; v[7] = u.y;
    }
#pragma unroll
    for (int j = 0; j < 8; j++) v[j] += vS[384 + c0 * 8 + j];
    // LN2
    s = 0.f; ss = 0.f;
#pragma unroll
    for (int j = 0; j < 8; j++) { s += v[j]; ss += v[j] * v[j]; }
    s = red16(s); ss = red16(ss);
    mu = s * (1.0f / 128.0f);
    var = ss * (1.0f / 128.0f) - mu * mu;
    inv = rsqrtf(var + 1e-5f);

    int row = base_row + r;
    float* embp = (float*)g_edge_emb4;
    float e8[8];
    float p1 = 0.f, p2 = 0.f;
#pragma unroll
    for (int j = 0; j < 8; j++) {
        int col = c0 * 8 + j;
        float e = (v[j] - mu) * inv * vS[512 + col] + vS[640 + col];
        e8[j] = e;
        p1 += e * vS[768 + col];
        p2 += e * vS[896 + col];
    }
    *(float4*)&embp[row * 128 + c0 * 8]     = make_float4(e8[0], e8[1], e8[2], e8[3]);
    *(float4*)&embp[row * 128 + c0 * 8 + 4] = make_float4(e8[4], e8[5], e8[6], e8[7]);
    p1 = red16(p1); p2 = red16(p2);
    if (c0 == 0) { g_se[0][row] = p1; g_se[1][row] = p2; }
}

// ---------------- CSR build ----------------
__global__ void zero_kernel() {
    int i = blockIdx.x * blockDim.x + threadIdx.x;
    float* nodep = (float*)g_node4;
    if (i < BATCH * NN * D) nodep[i] = 0.f;
    if (i < NN) { g_cnt[i] = 0; g_cur[i] = 0; }
}
__global__ void hist_kernel(const int* __restrict__ src, const int* __restrict__ dst) {
    int p = blockIdx.x * blockDim.x + threadIdx.x;
    if (p >= 2 * E) return;
    int n = (p < E) ? src[p] : dst[p - E];
    atomicAdd(&g_cnt[n], 1);
}
__global__ __launch_bounds__(1024) void scan_kernel() {
    __shared__ int tot[1024];
    const int PT = 10;
    int t = threadIdx.x;
    int base = t * PT;
    int loc[PT];
    int s = 0;
#pragma unroll
    for (int i = 0; i < PT; i++) {
        int idx = base + i;
        int v = (idx < NN) ? g_cnt[idx] : 0;
        loc[i] = s; s += v;
    }
    tot[t] = s;
    __syncthreads();
    for (int o = 1; o < 1024; o <<= 1) {
        int v = (t >= o) ? tot[t - o] : 0;
        __syncthreads();
        tot[t] += v;
        __syncthreads();
    }
    int excl = (t == 0) ? 0 : tot[t - 1];
#pragma unroll
    for (int i = 0; i < PT; i++) {
        int idx = base + i;
        if (idx < NN) g_off[idx] = excl + loc[i];
    }
    if (t == 1023) g_off[NN] = tot[1023];
}
__global__ void scatter_kernel(const int* __restrict__ src, const int* __restrict__ dst) {
    int p = blockIdx.x * blockDim.x + threadIdx.x;
    if (p >= 2 * E) return;
    int n = (p < E) ? src[p] : dst[p - E];
    int pos = atomicAdd(&g_cur[n], 1);
    g_plist[g_off[n] + pos] = p;
}

// ---------------- message passing: one warp per node ----------------
__global__ __launch_bounds__(256) void mp_kernel(
    const float* __restrict__ watt, const float* __restrict__ batt_p, int round)
{
    int w = threadIdx.x >> 5, lane = threadIdx.x & 31;
    int n = blockIdx.x * 8 + w;
    int b = blockIdx.y;
    if (n >= NN) return;
    int off = g_off[n];
    int cnt = g_off[n + 1] - off;
    if (cnt == 0) return;

    float batt = batt_p[0];
    float* nrow = ((float*)g_node4) + (b * NN + n) * D;

    float4 nv = reinterpret_cast<float4*>(nrow)[lane];
    float4 wv = reinterpret_cast<const float4*>(watt)[lane];
    float sn = nv.x * wv.x + nv.y * wv.y + nv.z * wv.z + nv.w * wv.w;
    sn = red32(sn);

    const float* se = g_se[round] + b * E;

    float m = -1e30f, d = 0.f;
    for (int i = lane; i < cnt; i += 32) {
        int p = g_plist[off + i];
        int e = (p < E) ? p : p - E;
        float sv = sn + se[e] + batt;
        sv = (sv > 0.f) ? sv : 0.2f * sv;
        if (sv > m) { d = d * __expf(m - sv) + 1.f; m = sv; }
        else        { d += __expf(sv - m); }
    }
#pragma unroll
    for (int o = 16; o > 0; o >>= 1) {
        float mo = __shfl_xor_sync(0xffffffffu, m, o);
        float dq = __shfl_xor_sync(0xffffffffu, d, o);
        float M = fmaxf(m, mo);
        d = d * __expf(m - M) + dq * __expf(mo - M);
        m = M;
    }
    float invd = 1.0f / d;

    const float* embp = (const float*)g_edge_emb4;
    float4 acc = make_float4(0.f, 0.f, 0.f, 0.f);
    for (int i = 0; i < cnt; i++) {
        int p = g_plist[off + i];
        int e = (p < E) ? p : p - E;
        float sv = sn + se[e] + batt;
        sv = (sv > 0.f) ? sv : 0.2f * sv;
        float wt = __expf(sv - m) * invd;
        float4 ev = reinterpret_cast<const float4*>(embp + (b * E + e) * D)[lane];
        acc.x += wt * ev.x; acc.y += wt * ev.y; acc.z += wt * ev.z; acc.w += wt * ev.w;
    }
    float4 outv;
    outv.x = gelu_exact(acc.x); outv.y = gelu_exact(acc.y);
    outv.z = gelu_exact(acc.z); outv.w = gelu_exact(acc.w);
    reinterpret_cast<float4*>(nrow)[lane] = outv;
}

// ---------------- node-side decoder precompute ----------------
__global__ __launch_bounds__(256) void p_kernel(const float* __restrict__ dec_w1) {
    __shared__ float nodeS[RPB * 129];
    __shared__ alignas(16) float WS[16 * 256];

    int t = threadIdx.x;
    int r = t >> 4, c0 = t & 15;
    int b = blockIdx.z, c = blockIdx.y;
    int n0 = blockIdx.x * RPB;
    const float* nodep = (const float*)g_node4;

    for (int i = t; i < RPB * D; i += 256) {
        int rr = i >> 7, k = i & 127;
        nodeS[rr * 129 + k] = nodep[(b * NN + n0 + rr) * D + k];
    }
    unsigned long long acc[8];
#pragma unroll
    for (int j = 0; j < 8; j++) acc[j] = 0ull;

    const float* Wbase = dec_w1 + c * D * 256;
    for (int kc = 0; kc < 8; kc++) {
        __syncthreads();
        for (int i = t; i < 16 * 256 / 4; i += 256)
            ((float4*)WS)[i] = ((const float4*)(Wbase + kc * 16 * 256))[i];
        __syncthreads();
#pragma unroll
        for (int k = 0; k < 16; k++) {
            unsigned long long ap = pack2(nodeS[r * 129 + kc * 16 + k]);
            ulonglong2 w01 = *(const ulonglong2*)&WS[k * 256 + c0 * 16];
            ulonglong2 w23 = *(const ulonglong2*)&WS[k * 256 + c0 * 16 + 4];
            ulonglong2 w45 = *(const ulonglong2*)&WS[k * 256 + c0 * 16 + 8];
            ulonglong2 w67 = *(const ulonglong2*)&WS[k * 256 + c0 * 16 + 12];
            ffma2(acc[0], ap, w01.x); ffma2(acc[1], ap, w01.y);
            ffma2(acc[2], ap, w23.x); ffma2(acc[3], ap, w23.y);
            ffma2(acc[4], ap, w45.x); ffma2(acc[5], ap, w45.y);
            ffma2(acc[6], ap, w67.x); ffma2(acc[7], ap, w67.y);
        }
    }
    float* P = (float*)(c == 0 ? g_P1_4 : g_P2_4) + (b * NN + n0 + r) * 256;
#pragma unroll
    for (int j = 0; j < 8; j++) {
        float2 u = unpack2(acc[j]);
        *(float2*)&P[c0 * 16 + 2 * j] = u;
    }
}

// ---------------- decoder GEMM A: z1 = gelu(emb@W1c + P1[src] + P2[dst] + b1) ----------------
// block: 64 rows x 256 cols, 256 threads; thread tile 8 rows x 8 cols
__global__ __launch_bounds__(256, 2) void gemmA_kernel(
    const float* __restrict__ dw1, const float* __restrict__ db1,
    const int* __restrict__ src, const int* __restrict__ dst)
{
    __shared__ float AS[64][17];
    __shared__ alignas(16) float BS[16][256];
    __shared__ int srcS[64], dstS[64];

    int t = threadIdx.x;
    int tx = t & 31, ty = t >> 5;
    int g0 = blockIdx.x * 64;
    if (t < 64) { int e = (g0 + t) % E; srcS[t] = src[e]; dstS[t] = dst[e]; }

    unsigned long long acc[8][4];
#pragma unroll
    for (int i = 0; i < 8; i++)
#pragma unroll
        for (int j = 0; j < 4; j++) acc[i][j] = 0ull;

    const float* W = dw1 + 256 * 256;
    const float* emb = (const float*)g_edge_emb4;
    int arow = t >> 2, aq = t & 3;

    for (int kc = 0; kc < 8; kc++) {
        __syncthreads();
        float4 av = *(const float4*)&emb[(g0 + arow) * 128 + kc * 16 + aq * 4];
        AS[arow][aq * 4 + 0] = av.x; AS[arow][aq * 4 + 1] = av.y;
        AS[arow][aq * 4 + 2] = av.z; AS[arow][aq * 4 + 3] = av.w;
#pragma unroll
        for (int q = 0; q < 4; q++)
            ((float4*)BS)[t + 256 * q] = ((const float4*)(W + kc * 16 * 256))[t + 256 * q];
        __syncthreads();
#pragma unroll
        for (int k = 0; k < 16; k++) {
            ulonglong2 b01 = *(const ulonglong2*)&BS[k][tx * 8];
            ulonglong2 b23 = *(const ulonglong2*)&BS[k][tx * 8 + 4];
#pragma unroll
            for (int i = 0; i < 8; i++) {
                unsigned long long ap = pack2(AS[ty * 8 + i][k]);
                ffma2(acc[i][0], ap, b01.x);
                ffma2(acc[i][1], ap, b01.y);
                ffma2(acc[i][2], ap, b23.x);
                ffma2(acc[i][3], ap, b23.y);
            }
        }
    }

    float* z1 = (float*)g_z1_4;
    float4 bca = *(const float4*)&db1[tx * 8];
    float4 bcb = *(const float4*)&db1[tx * 8 + 4];
    int bb = g0 / E;  // 64 | E, so no straddle
#pragma unroll
    for (int i = 0; i < 8; i++) {
        int row = g0 + ty * 8 + i;
        const float* P1r = ((const float*)g_P1_4) + (bb * NN + srcS[ty * 8 + i]) * 256;
        const float* P2r = ((const float*)g_P2_4) + (bb * NN + dstS[ty * 8 + i]) * 256;
        float4 p1a = *(const float4*)&P1r[tx * 8];
        float4 p1b = *(const float4*)&P1r[tx * 8 + 4];
        float4 p2a = *(const float4*)&P2r[tx * 8];
        float4 p2b = *(const float4*)&P2r[tx * 8 + 4];
        float2 u0 = unpack2(acc[i][0]), u1 = unpack2(acc[i][1]);
        float2 u2 = unpack2(acc[i][2]), u3 = unpack2(acc[i][3]);
        float4 oa, ob;
        oa.x = gelu_exact(u0.x + bca.x + p1a.x + p2a.x);
        oa.y = gelu_exact(u0.y + bca.y + p1a.y + p2a.y);
        oa.z = gelu_exact(u1.x + bca.z + p1a.z + p2a.z);
        oa.w = gelu_exact(u1.y + bca.w + p1a.w + p2a.w);
        ob.x = gelu_exact(u2.x + bcb.x + p1b.x + p2b.x);
        ob.y = gelu_exact(u2.y + bcb.y + p1b.y + p2b.y);
        ob.z = gelu_exact(u3.x + bcb.z + p1b.z + p2b.z);
        ob.w = gelu_exact(u3.y + bcb.w + p1b.w + p2b.w);
        *(float4*)&z1[row * 256 + tx * 8]     = oa;
        *(float4*)&z1[row * 256 + tx * 8 + 4] = ob;
    }
}

// ---------------- decoder GEMM B + output: out = gelu(z1@W2 + b2) . w3 + b3 ----------------
// block: 64 rows x 128 cols, 256 threads; thread tile 8 rows x 4 cols
__global__ __launch_bounds__(256, 2) void gemmB_kernel(
    const float* __restrict__ dw2, const float* __restrict__ db2,
    const float* __restrict__ dw3, const float* __restrict__ db3,
    float* __restrict__ out)
{
    __shared__ float AS[64][17];
    __shared__ alignas(16) float BS[16][128];

    int t = threadIdx.x;
    int tx = t & 31, ty = t >> 5;
    int g0 = blockIdx.x * 64;

    unsigned long long acc[8][2];
#pragma unroll
    for (int i = 0; i < 8; i++) { acc[i][0] = 0ull; acc[i][1] = 0ull; }

    const float* z1 = (const float*)g_z1_4;
    int arow = t >> 2, aq = t & 3;

    for (int kc = 0; kc < 16; kc++) {
        __syncthreads();
        float4 av = *(const float4*)&z1[(g0 + arow) * 256 + kc * 16 + aq * 4];
        AS[arow][aq * 4 + 0] = av.x; AS[arow][aq * 4 + 1] = av.y;
        AS[arow][aq * 4 + 2] = av.z; AS[arow][aq * 4 + 3] = av.w;
#pragma unroll
        for (int q = 0; q < 2; q++)
            ((float4*)BS)[t + 256 * q] = ((const float4*)(dw2 + kc * 16 * 128))[t + 256 * q];
        __syncthreads();
#pragma unroll
        for (int k = 0; k < 16; k++) {
            ulonglong2 bv = *(const ulonglong2*)&BS[k][tx * 4];
#pragma unroll
            for (int i = 0; i < 8; i++) {
                unsigned long long ap = pack2(AS[ty * 8 + i][k]);
                ffma2(acc[i][0], ap, bv.x);
                ffma2(acc[i][1], ap, bv.y);
            }
        }
    }

    float4 w3v = *(const float4*)&dw3[tx * 4];
    float4 b2v = *(const float4*)&db2[tx * 4];
    float bias3 = db3[0];
#pragma unroll
    for (int i = 0; i < 8; i++) {
        float2 u0 = unpack2(acc[i][0]);
        float2 u1 = unpack2(acc[i][1]);
        float s = gelu_exact(u0.x + b2v.x) * w3v.x
                + gelu_exact(u0.y + b2v.y) * w3v.y
                + gelu_exact(u1.x + b2v.z) * w3v.z
                + gelu_exact(u1.y + b2v.w) * w3v.w;
        s = red32(s);
        if (tx == 0) out[g0 + ty * 8 + i] = s + bias3;
    }
}

// ---------------- launch ----------------
extern "C" void kernel_launch(void* const* d_in, const int* in_sizes, int n_in,
                              void* d_out, int out_size)
{
    const float* xf    = (const float*)d_in[0];
    const float* w1    = (const float*)d_in[1];
    const float* b1    = (const float*)d_in[2];
    const float* g1    = (const float*)d_in[3];
    const float* be1   = (const float*)d_in[4];
    const float* w2    = (const float*)d_in[5];
    const float* b2    = (const float*)d_in[6];
    const float* g2    = (const float*)d_in[7];
    const float* be2   = (const float*)d_in[8];
    const float* watt1 = (const float*)d_in[9];
    const float* batt1 = (const float*)d_in[10];
    const float* watt2 = (const float*)d_in[11];
    const float* batt2 = (const float*)d_in[12];
    const float* dw1   = (const float*)d_in[13];
    const float* db1   = (const float*)d_in[14];
    const float* dw2   = (const float*)d_in[15];
    const float* db2   = (const float*)d_in[16];
    const float* dw3   = (const float*)d_in[17];
    const float* db3   = (const float*)d_in[18];
    const int*   src   = (const int*)d_in[19];
    const int*   dst   = (const int*)d_in[20];
    float* out = (float*)d_out;

    enc_kernel<<<(BATCH * E) / RPB, 256>>>(xf, w1, b1, g1, be1, w2, b2, g2, be2, watt1, watt2);

    zero_kernel<<<(BATCH * NN * D + 255) / 256, 256>>>();
    hist_kernel<<<(2 * E + 255) / 256, 256>>>(src, dst);
    scan_kernel<<<1, 1024>>>();
    scatter_kernel<<<(2 * E + 255) / 256, 256>>>(src, dst);

    mp_kernel<<<dim3(NN / 8, BATCH), 256>>>(watt1, batt1, 0);
    mp_kernel<<<dim3(NN / 8, BATCH), 256>>>(watt2, batt2, 1);

    p_kernel<<<dim3(NN / RPB, 2, BATCH), 256>>>(dw1);

    gemmA_kernel<<<(BATCH * E) / 64, 256>>>(dw1, db1, src, dst);
    gemmB_kernel<<<(BATCH * E) / 64, 256>>>(dw2, db2, dw3, db3, out);
}